// round 4
// baseline (speedup 1.0000x reference)
#include <cuda_runtime.h>
#include <cuda_bf16.h>
#include <math.h>
#include <stdint.h>

// ---------------------------------------------------------------------------
// GCN 2-layer forward:  out = log_softmax( A_hat @ relu(A_hat @ (x@W1) + b1) @ W2 + b2 )
// A_hat = D^{-1/2} (A + I) D^{-1/2}, deg counted on destination (in-degree + self-loop)
// CSR build (hist/scan/scatter) per call, GEMM-first then aggregate.
// Edge-index dtype is detected at runtime (int32 vs int64) by a probe kernel:
// JAX default config downgrades int64 -> int32 silently, so trust nothing.
// ---------------------------------------------------------------------------

#define NMAX 100000
#define EMAX 1600000
#define FIN  512
#define HID  128
#define NCLS 40

// --------------------------- device scratch --------------------------------
__device__ int   g_is64;
__device__ int   g_cnt[NMAX];
__device__ int   g_off[NMAX + 1];
__device__ int   g_cur[NMAX];
__device__ float g_dis[NMAX];
__device__ int   g_esrc[EMAX];
__device__ float g_enrm[EMAX];
__device__ __align__(128) float g_h1[(size_t)NMAX * HID];   // x @ W1
__device__ __align__(128) float g_a1[(size_t)NMAX * HID];   // relu(agg + b1)
__device__ __align__(128) float g_h2[(size_t)NMAX * NCLS];  // a1 @ W2

// --------------------------- index loading ---------------------------------
// slot = logical element index into the flattened [2*E] index array.
// int32 layout: value at p[slot]. int64 (LE) layout: low word at p[2*slot].
__device__ __forceinline__ int load_idx(const int* __restrict__ p, long long slot, int is64) {
    return is64 ? p[2 * slot] : p[slot];
}

// Probe: in int64 layout the odd 32-bit slots are high words (all 0 for values
// < 2^31). In int32 layout they are random node ids (virtually never all 0).
__global__ void k_probe(const unsigned* __restrict__ p) {
    unsigned nz = 0;
    for (int i = 1; i < 256; i += 2) nz |= p[i];
    g_is64 = (nz == 0u) ? 1 : 0;
}

// --------------------------- CSR construction ------------------------------
__global__ void k_init(int n) {
    int i = blockIdx.x * blockDim.x + threadIdx.x;
    if (i < n) { g_cnt[i] = 0; g_cur[i] = 0; }
}

__global__ void k_hist(const int* __restrict__ ei, int E) {
    int e = blockIdx.x * blockDim.x + threadIdx.x;
    int is64 = g_is64;
    if (e < E) {
        int d = load_idx(ei, (long long)E + e, is64);
        atomicAdd(&g_cnt[d], 1);
    }
}

// Single-block scan over N counters + dis = rsqrt(deg) (deg incl. self-loop)
__global__ void k_scan(int n) {
    __shared__ int part[1024];
    int t = threadIdx.x;
    int chunk = (n + 1023) / 1024;
    int beg = t * chunk;
    int end = min(beg + chunk, n);
    int s = 0;
    for (int i = beg; i < end; i++) s += g_cnt[i];
    part[t] = s;
    __syncthreads();
    for (int d = 1; d < 1024; d <<= 1) {
        int v = 0;
        if (t >= d) v = part[t - d];
        __syncthreads();
        if (t >= d) part[t] += v;
        __syncthreads();
    }
    int run = (t == 0) ? 0 : part[t - 1];
    for (int i = beg; i < end; i++) {
        int c = g_cnt[i];
        g_off[i] = run;
        run += c;
        g_dis[i] = rsqrtf((float)(c + 1));  // +1 self-loop
    }
    if (t == 1023) g_off[n] = part[1023];
}

__global__ void k_scatter(const int* __restrict__ ei, int E) {
    int e = blockIdx.x * blockDim.x + threadIdx.x;
    int is64 = g_is64;
    if (e < E) {
        int s = load_idx(ei, e, is64);
        int d = load_idx(ei, (long long)E + e, is64);
        int p = g_off[d] + atomicAdd(&g_cur[d], 1);
        g_esrc[p] = s;
        g_enrm[p] = g_dis[s] * g_dis[d];
    }
}

// --------------------------- GEMM1: [N,512] @ [512,128] -> g_h1 ------------
// BM=128, BN=128, BK=16, 256 threads, 8x8 per thread, scalar fmaf.
__global__ __launch_bounds__(256, 2) void k_gemm1(const float* __restrict__ X,
                                                  const float* __restrict__ W,
                                                  int M) {
    __shared__ float As[16][132];  // [k][m] transposed, +4 pad
    __shared__ float Bs[16][128];  // [k][n]

    int t  = threadIdx.x;
    int tx = t & 15;
    int ty = t >> 4;
    int blockRow = blockIdx.x * 128;

    const int c0 = tx * 4;        // cols c0..c0+3
    const int c1 = 64 + tx * 4;   // cols c1..c1+3

    float acc[8][8];
#pragma unroll
    for (int i = 0; i < 8; i++)
#pragma unroll
        for (int j = 0; j < 8; j++) acc[i][j] = 0.f;

    for (int kt = 0; kt < FIN; kt += 16) {
#pragma unroll
        for (int i = 0; i < 2; i++) {
            int slot = t + i * 256;           // 0..511
            int r  = slot >> 2;               // 0..127
            int c4 = slot & 3;                // 0..3
            int gr = blockRow + r;
            if (gr >= M) gr = M - 1;
            float4 v = *(const float4*)&X[(size_t)gr * FIN + kt + c4 * 4];
            As[c4 * 4 + 0][r] = v.x;
            As[c4 * 4 + 1][r] = v.y;
            As[c4 * 4 + 2][r] = v.z;
            As[c4 * 4 + 3][r] = v.w;
        }
#pragma unroll
        for (int i = 0; i < 2; i++) {
            int slot = t + i * 256;           // 0..511
            int r  = slot >> 5;               // 0..15
            int c4 = slot & 31;               // 0..31
            float4 v = *(const float4*)&W[(size_t)(kt + r) * HID + c4 * 4];
            *(float4*)&Bs[r][c4 * 4] = v;
        }
        __syncthreads();

#pragma unroll
        for (int k = 0; k < 16; k++) {
            float a[8], b[8];
            float4 a0 = *(const float4*)&As[k][ty * 8];
            float4 a1 = *(const float4*)&As[k][ty * 8 + 4];
            a[0] = a0.x; a[1] = a0.y; a[2] = a0.z; a[3] = a0.w;
            a[4] = a1.x; a[5] = a1.y; a[6] = a1.z; a[7] = a1.w;
            float4 b0 = *(const float4*)&Bs[k][c0];
            float4 b1v = *(const float4*)&Bs[k][c1];
            b[0] = b0.x; b[1] = b0.y; b[2] = b0.z; b[3] = b0.w;
            b[4] = b1v.x; b[5] = b1v.y; b[6] = b1v.z; b[7] = b1v.w;
#pragma unroll
            for (int i = 0; i < 8; i++)
#pragma unroll
                for (int j = 0; j < 8; j++)
                    acc[i][j] = fmaf(a[i], b[j], acc[i][j]);
        }
        __syncthreads();
    }

#pragma unroll
    for (int i = 0; i < 8; i++) {
        int gr = blockRow + ty * 8 + i;
        if (gr < M) {
            *(float4*)&g_h1[(size_t)gr * HID + c0] =
                make_float4(acc[i][0], acc[i][1], acc[i][2], acc[i][3]);
            *(float4*)&g_h1[(size_t)gr * HID + c1] =
                make_float4(acc[i][4], acc[i][5], acc[i][6], acc[i][7]);
        }
    }
}

// ------------------ Aggregation 1: warp per node, 128 feats ----------------
__global__ void k_agg1(const float* __restrict__ b1, int n) {
    int w = (blockIdx.x * blockDim.x + threadIdx.x) >> 5;
    if (w >= n) return;
    int l = threadIdx.x & 31;

    float di = g_dis[w];
    float dself = di * di;

    float4 acc = *(const float4*)&g_h1[(size_t)w * HID + l * 4];
    acc.x *= dself; acc.y *= dself; acc.z *= dself; acc.w *= dself;

    int beg = g_off[w], end = g_off[w + 1];
    for (int p = beg; p < end; p++) {
        int   s  = g_esrc[p];
        float wt = g_enrm[p];
        float4 v = *(const float4*)&g_h1[(size_t)s * HID + l * 4];
        acc.x = fmaf(v.x, wt, acc.x);
        acc.y = fmaf(v.y, wt, acc.y);
        acc.z = fmaf(v.z, wt, acc.z);
        acc.w = fmaf(v.w, wt, acc.w);
    }
    float4 bb = *(const float4*)&b1[l * 4];
    acc.x = fmaxf(acc.x + bb.x, 0.f);
    acc.y = fmaxf(acc.y + bb.y, 0.f);
    acc.z = fmaxf(acc.z + bb.z, 0.f);
    acc.w = fmaxf(acc.w + bb.w, 0.f);
    *(float4*)&g_a1[(size_t)w * HID + l * 4] = acc;
}

// --------------------- GEMM2: [N,128] @ [128,40] -> g_h2 -------------------
__global__ __launch_bounds__(256, 2) void k_gemm2(const float* __restrict__ W2, int M) {
    __shared__ float As[16][260];  // [k][m] transposed, +4 pad
    __shared__ float Ws[16][NCLS];

    int t  = threadIdx.x;
    int tx = t & 7;    // col group: tx*5 .. tx*5+4
    int ty = t >> 3;   // row group: ty*8 .. ty*8+7
    int blockRow = blockIdx.x * 256;

    float acc[8][5];
#pragma unroll
    for (int i = 0; i < 8; i++)
#pragma unroll
        for (int j = 0; j < 5; j++) acc[i][j] = 0.f;

    for (int kt = 0; kt < HID; kt += 16) {
#pragma unroll
        for (int i = 0; i < 4; i++) {
            int slot = t + i * 256;           // 0..1023
            int r  = slot >> 2;               // 0..255
            int c4 = slot & 3;
            int gr = blockRow + r;
            if (gr >= M) gr = M - 1;
            float4 v = *(const float4*)&g_a1[(size_t)gr * HID + kt + c4 * 4];
            As[c4 * 4 + 0][r] = v.x;
            As[c4 * 4 + 1][r] = v.y;
            As[c4 * 4 + 2][r] = v.z;
            As[c4 * 4 + 3][r] = v.w;
        }
        if (t < 160) {
            int r  = t / 10;
            int c4 = t % 10;
            float4 v = *(const float4*)&W2[(size_t)(kt + r) * NCLS + c4 * 4];
            *(float4*)&Ws[r][c4 * 4] = v;
        }
        __syncthreads();

#pragma unroll
        for (int k = 0; k < 16; k++) {
            float a[8], wv[5];
#pragma unroll
            for (int i = 0; i < 8; i++) a[i] = As[k][ty * 8 + i];
#pragma unroll
            for (int j = 0; j < 5; j++) wv[j] = Ws[k][tx * 5 + j];
#pragma unroll
            for (int i = 0; i < 8; i++)
#pragma unroll
                for (int j = 0; j < 5; j++) acc[i][j] = fmaf(a[i], wv[j], acc[i][j]);
        }
        __syncthreads();
    }

#pragma unroll
    for (int i = 0; i < 8; i++) {
        int gr = blockRow + ty * 8 + i;
        if (gr < M) {
#pragma unroll
            for (int j = 0; j < 5; j++)
                g_h2[(size_t)gr * NCLS + tx * 5 + j] = acc[i][j];
        }
    }
}

// ------- Aggregation 2 + bias + log_softmax: warp per node, 40 feats -------
__global__ void k_agg2(const float* __restrict__ b2, float* __restrict__ out, int n) {
    int w = (blockIdx.x * blockDim.x + threadIdx.x) >> 5;
    if (w >= n) return;
    int l = threadIdx.x & 31;
    bool has2 = (l < 8);

    float di = g_dis[w];
    float dself = di * di;

    const float* row = &g_h2[(size_t)w * NCLS];
    float acc0 = row[l] * dself;
    float acc1 = has2 ? row[32 + l] * dself : 0.f;

    int beg = g_off[w], end = g_off[w + 1];
    for (int p = beg; p < end; p++) {
        int   s  = g_esrc[p];
        float wt = g_enrm[p];
        const float* r2 = &g_h2[(size_t)s * NCLS];
        acc0 = fmaf(r2[l], wt, acc0);
        if (has2) acc1 = fmaf(r2[32 + l], wt, acc1);
    }
    acc0 += b2[l];
    if (has2) acc1 += b2[32 + l];

    float m = has2 ? fmaxf(acc0, acc1) : acc0;
#pragma unroll
    for (int o = 16; o >= 1; o >>= 1) m = fmaxf(m, __shfl_xor_sync(0xffffffffu, m, o));
    float e = expf(acc0 - m) + (has2 ? expf(acc1 - m) : 0.f);
#pragma unroll
    for (int o = 16; o >= 1; o >>= 1) e += __shfl_xor_sync(0xffffffffu, e, o);
    float lse = m + logf(e);

    out[(size_t)w * NCLS + l] = acc0 - lse;
    if (has2) out[(size_t)w * NCLS + 32 + l] = acc1 - lse;
}

// --------------------------------- launch ----------------------------------
extern "C" void kernel_launch(void* const* d_in, const int* in_sizes, int n_in,
                              void* d_out, int out_size) {
    const float* x  = (const float*)d_in[0];
    const int*   ei = (const int*)d_in[1];
    const float* W1 = (const float*)d_in[2];
    const float* b1 = (const float*)d_in[3];
    const float* W2 = (const float*)d_in[4];
    const float* b2 = (const float*)d_in[5];
    float*       out = (float*)d_out;

    int N = in_sizes[0] / FIN;       // 100000
    int E = in_sizes[1] / 2;         // 1600000 (elements of [2,E] index array)

    // dtype probe + CSR build
    k_probe<<<1, 1>>>((const unsigned*)d_in[1]);
    k_init<<<(N + 255) / 256, 256>>>(N);
    k_hist<<<(E + 255) / 256, 256>>>(ei, E);
    k_scan<<<1, 1024>>>(N);
    k_scatter<<<(E + 255) / 256, 256>>>(ei, E);

    // Layer 1
    k_gemm1<<<(N + 127) / 128, 256>>>(x, W1, N);
    k_agg1<<<(N * 32 + 255) / 256, 256>>>(b1, N);

    // Layer 2 + log_softmax
    k_gemm2<<<(N + 255) / 256, 256>>>(W2, N);
    k_agg2<<<(N * 32 + 255) / 256, 256>>>(b2, out, N);
}

// round 5
// speedup vs baseline: 1.3341x; 1.3341x over previous
#include <cuda_runtime.h>
#include <cuda_bf16.h>
#include <math.h>
#include <stdint.h>

// ---------------------------------------------------------------------------
// GCN 2-layer forward:  out = log_softmax( A_hat @ relu(A_hat @ (x@W1) + b1) @ W2 + b2 )
// R5: parallel decoupled scan (was 160us single-block) + packed f32x2 GEMM1.
// ---------------------------------------------------------------------------

#define NMAX 100000
#define EMAX 1600000
#define FIN  512
#define HID  128
#define NCLS 40
#define NBLK ((NMAX + 1023) / 1024)   // 98 scan blocks

typedef unsigned long long ull;

// --------------------------- device scratch --------------------------------
__device__ int   g_is64;
__device__ int   g_cnt[NMAX];
__device__ int   g_off[NMAX + 1];
__device__ int   g_cur[NMAX];
__device__ float g_dis[NMAX];
__device__ int   g_blksum[NBLK];
__device__ int   g_blkoff[NBLK];
__device__ int   g_esrc[EMAX];
__device__ float g_enrm[EMAX];
__device__ __align__(128) float g_h1[(size_t)NMAX * HID];
__device__ __align__(128) float g_a1[(size_t)NMAX * HID];
__device__ __align__(128) float g_h2[(size_t)NMAX * NCLS];

// --------------------------- helpers ---------------------------------------
__device__ __forceinline__ int load_idx(const int* __restrict__ p, long long slot, int is64) {
    return is64 ? p[2 * slot] : p[slot];
}
__device__ __forceinline__ ull pack_dup_f32(float a) {
    ull r;
    asm("mov.b64 %0, {%1, %1};" : "=l"(r) : "r"(__float_as_uint(a)));
    return r;
}
__device__ __forceinline__ void fma_f32x2(ull& d, ull a, ull b) {
    asm("fma.rn.f32x2 %0, %1, %2, %0;" : "+l"(d) : "l"(a), "l"(b));
}
__device__ __forceinline__ float2 ull_as_f2(ull u) {
    float2 f;
    asm("mov.b64 {%0, %1}, %2;" : "=f"(f.x), "=f"(f.y) : "l"(u));
    return f;
}

// Probe edge-index dtype: int64 layout has all-zero odd 32-bit words.
__global__ void k_probe(const unsigned* __restrict__ p) {
    unsigned nz = 0;
    for (int i = 1; i < 256; i += 2) nz |= p[i];
    g_is64 = (nz == 0u) ? 1 : 0;
}

// --------------------------- CSR construction ------------------------------
__global__ void k_init(int n) {
    int i = blockIdx.x * blockDim.x + threadIdx.x;
    if (i < n) { g_cnt[i] = 0; g_cur[i] = 0; }
}

__global__ void k_hist(const int* __restrict__ ei, int E) {
    int e = blockIdx.x * blockDim.x + threadIdx.x;
    int is64 = g_is64;
    if (e < E) {
        int d = load_idx(ei, (long long)E + e, is64);
        atomicAdd(&g_cnt[d], 1);
    }
}

// Stage A: per-block sum of 1024 counters
__global__ void k_scanA(int n) {
    __shared__ int sh[1024];
    int t = threadIdx.x;
    int i = blockIdx.x * 1024 + t;
    int v = (i < n) ? g_cnt[i] : 0;
    sh[t] = v;
    __syncthreads();
#pragma unroll
    for (int d = 512; d > 0; d >>= 1) {
        if (t < d) sh[t] += sh[t + d];
        __syncthreads();
    }
    if (t == 0) g_blksum[blockIdx.x] = sh[0];
}

// Stage B: exclusive scan of NBLK block sums (1 small block)
__global__ void k_scanB(int nb) {
    __shared__ int sh[128];
    int t = threadIdx.x;
    int v = (t < nb) ? g_blksum[t] : 0;
    sh[t] = v;
    __syncthreads();
#pragma unroll
    for (int d = 1; d < 128; d <<= 1) {
        int u = 0;
        if (t >= d) u = sh[t - d];
        __syncthreads();
        if (t >= d) sh[t] += u;
        __syncthreads();
    }
    if (t < nb) g_blkoff[t] = sh[t] - v;
}

// Stage C: per-block exclusive scan + global offset; also g_dis
__global__ void k_scanC(int n) {
    __shared__ int sh[1024];
    int t = threadIdx.x;
    int i = blockIdx.x * 1024 + t;
    int c = (i < n) ? g_cnt[i] : 0;
    sh[t] = c;
    __syncthreads();
#pragma unroll
    for (int d = 1; d < 1024; d <<= 1) {
        int u = 0;
        if (t >= d) u = sh[t - d];
        __syncthreads();
        if (t >= d) sh[t] += u;
        __syncthreads();
    }
    if (i < n) {
        int off = g_blkoff[blockIdx.x] + sh[t] - c;
        g_off[i] = off;
        g_dis[i] = rsqrtf((float)(c + 1));   // +1 self-loop
        if (i == n - 1) g_off[n] = off + c;
    }
}

__global__ void k_scatter(const int* __restrict__ ei, int E) {
    int e = blockIdx.x * blockDim.x + threadIdx.x;
    int is64 = g_is64;
    if (e < E) {
        int s = load_idx(ei, e, is64);
        int d = load_idx(ei, (long long)E + e, is64);
        int p = g_off[d] + atomicAdd(&g_cur[d], 1);
        g_esrc[p] = s;
        g_enrm[p] = g_dis[s] * g_dis[d];
    }
}

// --------------------------- GEMM1: [N,512] @ [512,128] -> g_h1 ------------
// BM=128, BN=128, BK=16, 256 threads, 8x8 per thread, packed f32x2 FMAs.
__global__ __launch_bounds__(256, 2) void k_gemm1(const float* __restrict__ X,
                                                  const float* __restrict__ W,
                                                  int M) {
    __shared__ float As[16][132];  // [k][m] transposed, +4 pad
    __shared__ float Bs[16][128];  // [k][n]

    int t  = threadIdx.x;
    int tx = t & 15;
    int ty = t >> 4;
    int blockRow = blockIdx.x * 128;

    const int c0 = tx * 4;
    const int c1 = 64 + tx * 4;

    ull acc[8][4];
#pragma unroll
    for (int i = 0; i < 8; i++)
#pragma unroll
        for (int j = 0; j < 4; j++) acc[i][j] = 0ull;

    for (int kt = 0; kt < FIN; kt += 16) {
#pragma unroll
        for (int i = 0; i < 2; i++) {
            int slot = t + i * 256;
            int r  = slot >> 2;
            int c4 = slot & 3;
            int gr = blockRow + r;
            if (gr >= M) gr = M - 1;
            float4 v = *(const float4*)&X[(size_t)gr * FIN + kt + c4 * 4];
            As[c4 * 4 + 0][r] = v.x;
            As[c4 * 4 + 1][r] = v.y;
            As[c4 * 4 + 2][r] = v.z;
            As[c4 * 4 + 3][r] = v.w;
        }
#pragma unroll
        for (int i = 0; i < 2; i++) {
            int slot = t + i * 256;
            int r  = slot >> 5;
            int c4 = slot & 31;
            float4 v = *(const float4*)&W[(size_t)(kt + r) * HID + c4 * 4];
            *(float4*)&Bs[r][c4 * 4] = v;
        }
        __syncthreads();

#pragma unroll
        for (int k = 0; k < 16; k++) {
            ulonglong2 b01 = *(const ulonglong2*)&Bs[k][c0];
            ulonglong2 b23 = *(const ulonglong2*)&Bs[k][c1];
            ull b[4] = {b01.x, b01.y, b23.x, b23.y};
            float4 a0 = *(const float4*)&As[k][ty * 8];
            float4 a1 = *(const float4*)&As[k][ty * 8 + 4];
            float av[8] = {a0.x, a0.y, a0.z, a0.w, a1.x, a1.y, a1.z, a1.w};
#pragma unroll
            for (int i = 0; i < 8; i++) {
                ull a2 = pack_dup_f32(av[i]);
#pragma unroll
                for (int j = 0; j < 4; j++) fma_f32x2(acc[i][j], a2, b[j]);
            }
        }
        __syncthreads();
    }

#pragma unroll
    for (int i = 0; i < 8; i++) {
        int gr = blockRow + ty * 8 + i;
        if (gr < M) {
            float2 p0 = ull_as_f2(acc[i][0]);
            float2 p1 = ull_as_f2(acc[i][1]);
            float2 p2 = ull_as_f2(acc[i][2]);
            float2 p3 = ull_as_f2(acc[i][3]);
            *(float4*)&g_h1[(size_t)gr * HID + c0] = make_float4(p0.x, p0.y, p1.x, p1.y);
            *(float4*)&g_h1[(size_t)gr * HID + c1] = make_float4(p2.x, p2.y, p3.x, p3.y);
        }
    }
}

// ------------------ Aggregation 1: warp per node, 128 feats ----------------
__global__ void k_agg1(const float* __restrict__ b1, int n) {
    int w = (blockIdx.x * blockDim.x + threadIdx.x) >> 5;
    if (w >= n) return;
    int l = threadIdx.x & 31;

    float di = g_dis[w];
    float dself = di * di;

    float4 acc = *(const float4*)&g_h1[(size_t)w * HID + l * 4];
    acc.x *= dself; acc.y *= dself; acc.z *= dself; acc.w *= dself;

    int beg = g_off[w], end = g_off[w + 1];
    for (int p = beg; p < end; p++) {
        int   s  = g_esrc[p];
        float wt = g_enrm[p];
        float4 v = *(const float4*)&g_h1[(size_t)s * HID + l * 4];
        acc.x = fmaf(v.x, wt, acc.x);
        acc.y = fmaf(v.y, wt, acc.y);
        acc.z = fmaf(v.z, wt, acc.z);
        acc.w = fmaf(v.w, wt, acc.w);
    }
    float4 bb = *(const float4*)&b1[l * 4];
    acc.x = fmaxf(acc.x + bb.x, 0.f);
    acc.y = fmaxf(acc.y + bb.y, 0.f);
    acc.z = fmaxf(acc.z + bb.z, 0.f);
    acc.w = fmaxf(acc.w + bb.w, 0.f);
    *(float4*)&g_a1[(size_t)w * HID + l * 4] = acc;
}

// --------------------- GEMM2: [N,128] @ [128,40] -> g_h2 -------------------
__global__ __launch_bounds__(256, 2) void k_gemm2(const float* __restrict__ W2, int M) {
    __shared__ float As[16][260];
    __shared__ float Ws[16][NCLS];

    int t  = threadIdx.x;
    int tx = t & 7;
    int ty = t >> 3;
    int blockRow = blockIdx.x * 256;

    float acc[8][5];
#pragma unroll
    for (int i = 0; i < 8; i++)
#pragma unroll
        for (int j = 0; j < 5; j++) acc[i][j] = 0.f;

    for (int kt = 0; kt < HID; kt += 16) {
#pragma unroll
        for (int i = 0; i < 4; i++) {
            int slot = t + i * 256;
            int r  = slot >> 2;
            int c4 = slot & 3;
            int gr = blockRow + r;
            if (gr >= M) gr = M - 1;
            float4 v = *(const float4*)&g_a1[(size_t)gr * HID + kt + c4 * 4];
            As[c4 * 4 + 0][r] = v.x;
            As[c4 * 4 + 1][r] = v.y;
            As[c4 * 4 + 2][r] = v.z;
            As[c4 * 4 + 3][r] = v.w;
        }
        if (t < 160) {
            int r  = t / 10;
            int c4 = t % 10;
            float4 v = *(const float4*)&W2[(size_t)(kt + r) * NCLS + c4 * 4];
            *(float4*)&Ws[r][c4 * 4] = v;
        }
        __syncthreads();

#pragma unroll
        for (int k = 0; k < 16; k++) {
            float a[8], wv[5];
#pragma unroll
            for (int i = 0; i < 8; i++) a[i] = As[k][ty * 8 + i];
#pragma unroll
            for (int j = 0; j < 5; j++) wv[j] = Ws[k][tx * 5 + j];
#pragma unroll
            for (int i = 0; i < 8; i++)
#pragma unroll
                for (int j = 0; j < 5; j++) acc[i][j] = fmaf(a[i], wv[j], acc[i][j]);
        }
        __syncthreads();
    }

#pragma unroll
    for (int i = 0; i < 8; i++) {
        int gr = blockRow + ty * 8 + i;
        if (gr < M) {
#pragma unroll
            for (int j = 0; j < 5; j++)
                g_h2[(size_t)gr * NCLS + tx * 5 + j] = acc[i][j];
        }
    }
}

// ------- Aggregation 2 + bias + log_softmax: warp per node, 40 feats -------
__global__ void k_agg2(const float* __restrict__ b2, float* __restrict__ out, int n) {
    int w = (blockIdx.x * blockDim.x + threadIdx.x) >> 5;
    if (w >= n) return;
    int l = threadIdx.x & 31;
    bool has2 = (l < 8);

    float di = g_dis[w];
    float dself = di * di;

    const float* row = &g_h2[(size_t)w * NCLS];
    float acc0 = row[l] * dself;
    float acc1 = has2 ? row[32 + l] * dself : 0.f;

    int beg = g_off[w], end = g_off[w + 1];
    for (int p = beg; p < end; p++) {
        int   s  = g_esrc[p];
        float wt = g_enrm[p];
        const float* r2 = &g_h2[(size_t)s * NCLS];
        acc0 = fmaf(r2[l], wt, acc0);
        if (has2) acc1 = fmaf(r2[32 + l], wt, acc1);
    }
    acc0 += b2[l];
    if (has2) acc1 += b2[32 + l];

    float m = has2 ? fmaxf(acc0, acc1) : acc0;
#pragma unroll
    for (int o = 16; o >= 1; o >>= 1) m = fmaxf(m, __shfl_xor_sync(0xffffffffu, m, o));
    float e = expf(acc0 - m) + (has2 ? expf(acc1 - m) : 0.f);
#pragma unroll
    for (int o = 16; o >= 1; o >>= 1) e += __shfl_xor_sync(0xffffffffu, e, o);
    float lse = m + logf(e);

    out[(size_t)w * NCLS + l] = acc0 - lse;
    if (has2) out[(size_t)w * NCLS + 32 + l] = acc1 - lse;
}

// --------------------------------- launch ----------------------------------
extern "C" void kernel_launch(void* const* d_in, const int* in_sizes, int n_in,
                              void* d_out, int out_size) {
    const float* x  = (const float*)d_in[0];
    const int*   ei = (const int*)d_in[1];
    const float* W1 = (const float*)d_in[2];
    const float* b1 = (const float*)d_in[3];
    const float* W2 = (const float*)d_in[4];
    const float* b2 = (const float*)d_in[5];
    float*       out = (float*)d_out;

    int N = in_sizes[0] / FIN;       // 100000
    int E = in_sizes[1] / 2;         // 1600000

    int nb = (N + 1023) / 1024;

    // dtype probe + CSR build (parallel scan)
    k_probe<<<1, 1>>>((const unsigned*)d_in[1]);
    k_init<<<(N + 255) / 256, 256>>>(N);
    k_hist<<<(E + 255) / 256, 256>>>(ei, E);
    k_scanA<<<nb, 1024>>>(N);
    k_scanB<<<1, 128>>>(nb);
    k_scanC<<<nb, 1024>>>(N);
    k_scatter<<<(E + 255) / 256, 256>>>(ei, E);

    // Layer 1
    k_gemm1<<<(N + 127) / 128, 256>>>(x, W1, N);
    k_agg1<<<(N * 32 + 255) / 256, 256>>>(b1, N);

    // Layer 2 + log_softmax
    k_gemm2<<<(N + 255) / 256, 256>>>(W2, N);
    k_agg2<<<(N * 32 + 255) / 256, 256>>>(b2, out, N);
}

// round 7
// speedup vs baseline: 1.8313x; 1.3726x over previous
#include <cuda_runtime.h>
#include <cuda_bf16.h>
#include <math.h>
#include <stdint.h>

// ---------------------------------------------------------------------------
// GCN 2-layer forward. R7: GEMM1 via mma.sync (HMMA, baseline PTX) with
// bf16 3-term split. tcgen05 is unavailable: harness compiles via compute_103
// (non-"a") virtual target, which rejects all arch-specific instructions.
// ---------------------------------------------------------------------------

#define NMAX 100000
#define EMAX 1600000
#define FIN  512
#define HID  128
#define NCLS 40
#define NBLK ((NMAX + 1023) / 1024)

typedef unsigned long long ull;

// --------------------------- device scratch --------------------------------
__device__ int   g_is64;
__device__ int   g_cnt[NMAX];
__device__ int   g_off[NMAX + 1];
__device__ int   g_cur[NMAX];
__device__ float g_dis[NMAX];
__device__ int   g_blksum[NBLK];
__device__ int   g_blkoff[NBLK];
__device__ int   g_esrc[EMAX];
__device__ float g_enrm[EMAX];
__device__ __align__(128) __nv_bfloat16 g_w1h[(size_t)HID * FIN];  // W1^T hi
__device__ __align__(128) __nv_bfloat16 g_w1l[(size_t)HID * FIN];  // W1^T lo
__device__ __align__(128) float g_h1[(size_t)NMAX * HID];
__device__ __align__(128) float g_a1[(size_t)NMAX * HID];
__device__ __align__(128) float g_h2[(size_t)NMAX * NCLS];

// --------------------------- helpers ---------------------------------------
__device__ __forceinline__ int load_idx(const int* __restrict__ p, long long slot, int is64) {
    return is64 ? p[2 * slot] : p[slot];
}
__global__ void k_probe(const unsigned* __restrict__ p) {
    unsigned nz = 0;
    for (int i = 1; i < 256; i += 2) nz |= p[i];
    g_is64 = (nz == 0u) ? 1 : 0;
}

// bf16x2 pack of hi parts and residual lo parts of 2 floats
__device__ __forceinline__ unsigned pack_hi2(float x, float y) {
    __nv_bfloat16 hx = __float2bfloat16(x), hy = __float2bfloat16(y);
    return (unsigned)__bfloat16_as_ushort(hx) | ((unsigned)__bfloat16_as_ushort(hy) << 16);
}
__device__ __forceinline__ unsigned pack_lo2(float x, float y) {
    __nv_bfloat16 hx = __float2bfloat16(x), hy = __float2bfloat16(y);
    __nv_bfloat16 lx = __float2bfloat16(x - __bfloat162float(hx));
    __nv_bfloat16 ly = __float2bfloat16(y - __bfloat162float(hy));
    return (unsigned)__bfloat16_as_ushort(lx) | ((unsigned)__bfloat16_as_ushort(ly) << 16);
}

#define MMA_BF16(c, a, b0, b1)                                                   \
    asm volatile("mma.sync.aligned.m16n8k16.row.col.f32.bf16.bf16.f32 "          \
        "{%0,%1,%2,%3}, {%4,%5,%6,%7}, {%8,%9}, {%0,%1,%2,%3};"                  \
        : "+f"((c)[0]), "+f"((c)[1]), "+f"((c)[2]), "+f"((c)[3])                 \
        : "r"((a)[0]), "r"((a)[1]), "r"((a)[2]), "r"((a)[3]), "r"(b0), "r"(b1))

// --------------------------- CSR construction ------------------------------
__global__ void k_init(int n) {
    int i = blockIdx.x * blockDim.x + threadIdx.x;
    if (i < n) { g_cnt[i] = 0; g_cur[i] = 0; }
}
__global__ void k_hist(const int* __restrict__ ei, int E) {
    int e = blockIdx.x * blockDim.x + threadIdx.x;
    int is64 = g_is64;
    if (e < E) atomicAdd(&g_cnt[load_idx(ei, (long long)E + e, is64)], 1);
}
__global__ void k_scanA(int n) {
    __shared__ int sh[1024];
    int t = threadIdx.x;
    int i = blockIdx.x * 1024 + t;
    sh[t] = (i < n) ? g_cnt[i] : 0;
    __syncthreads();
#pragma unroll
    for (int d = 512; d > 0; d >>= 1) {
        if (t < d) sh[t] += sh[t + d];
        __syncthreads();
    }
    if (t == 0) g_blksum[blockIdx.x] = sh[0];
}
__global__ void k_scanB(int nb) {
    __shared__ int sh[128];
    int t = threadIdx.x;
    int v = (t < nb) ? g_blksum[t] : 0;
    sh[t] = v;
    __syncthreads();
#pragma unroll
    for (int d = 1; d < 128; d <<= 1) {
        int u = 0;
        if (t >= d) u = sh[t - d];
        __syncthreads();
        if (t >= d) sh[t] += u;
        __syncthreads();
    }
    if (t < nb) g_blkoff[t] = sh[t] - v;
}
__global__ void k_scanC(int n) {
    __shared__ int sh[1024];
    int t = threadIdx.x;
    int i = blockIdx.x * 1024 + t;
    int c = (i < n) ? g_cnt[i] : 0;
    sh[t] = c;
    __syncthreads();
#pragma unroll
    for (int d = 1; d < 1024; d <<= 1) {
        int u = 0;
        if (t >= d) u = sh[t - d];
        __syncthreads();
        if (t >= d) sh[t] += u;
        __syncthreads();
    }
    if (i < n) {
        int off = g_blkoff[blockIdx.x] + sh[t] - c;
        g_off[i] = off;
        g_dis[i] = rsqrtf((float)(c + 1));
        if (i == n - 1) g_off[n] = off + c;
    }
}
__global__ void k_scatter(const int* __restrict__ ei, int E) {
    int e = blockIdx.x * blockDim.x + threadIdx.x;
    int is64 = g_is64;
    if (e < E) {
        int s = load_idx(ei, e, is64);
        int d = load_idx(ei, (long long)E + e, is64);
        int p = g_off[d] + atomicAdd(&g_cur[d], 1);
        g_esrc[p] = s;
        g_enrm[p] = g_dis[s] * g_dis[d];
    }
}

// ------------------ W1 split: fp32 [512,128] -> bf16 hi/lo W^T [128,512] ----
__global__ void k_wconv(const float* __restrict__ W1) {
    int i = blockIdx.x * blockDim.x + threadIdx.x;
    if (i < FIN * HID) {
        int k = i / HID, n = i % HID;
        float w = W1[i];
        __nv_bfloat16 h = __float2bfloat16(w);
        __nv_bfloat16 l = __float2bfloat16(w - __bfloat162float(h));
        g_w1h[(size_t)n * FIN + k] = h;
        g_w1l[(size_t)n * FIN + k] = l;
    }
}

// ---------- GEMM1 via mma.sync: [N,512] x [512,128] -> g_h1 ----------------
// CTA tile 128x128, K chunks of 32. 8 warps: warp tile 32(M) x 64(N).
// A split to bf16 hi/lo on the fly; B pre-split (g_w1h/g_w1l), [n][k] smem.
// 3 terms: ah*bh + ah*bl + al*bh, fp32 accum.
#define SA 40   // smem stride in halves (conflict-free fragment reads)

__global__ __launch_bounds__(256) void k_gemm1_mma(const float* __restrict__ X, int M) {
    __shared__ __nv_bfloat16 sAh[128 * SA];
    __shared__ __nv_bfloat16 sAl[128 * SA];
    __shared__ __nv_bfloat16 sBh[128 * SA];
    __shared__ __nv_bfloat16 sBl[128 * SA];

    int t    = threadIdx.x;
    int lane = t & 31;
    int wid  = t >> 5;
    int wm   = wid & 3;   // 0..3 : M groups of 32
    int wn   = wid >> 2;  // 0..1 : N groups of 64
    int blockRow = blockIdx.x * 128;

    float acc[2][8][4];
#pragma unroll
    for (int mi = 0; mi < 2; mi++)
#pragma unroll
        for (int ni = 0; ni < 8; ni++)
#pragma unroll
            for (int c = 0; c < 4; c++) acc[mi][ni][c] = 0.f;

    const int lg = lane >> 2;          // 0..7
    const int lk = (lane & 3) * 2;     // 0,2,4,6

    for (int ch = 0; ch < 16; ch++) {
        int kt = ch * 32;
        // A fill: 128 rows x 32 k, fp32 -> bf16 hi/lo
#pragma unroll
        for (int i = 0; i < 4; i++) {
            int f  = t + i * 256;        // 0..1023
            int r  = f >> 3;             // 0..127
            int c4 = f & 7;              // 0..7 -> k offset c4*4
            int gr = blockRow + r;
            if (gr >= M) gr = M - 1;
            float4 v = *(const float4*)&X[(size_t)gr * FIN + kt + c4 * 4];
            ull h = (ull)pack_hi2(v.x, v.y) | ((ull)pack_hi2(v.z, v.w) << 32);
            ull l = (ull)pack_lo2(v.x, v.y) | ((ull)pack_lo2(v.z, v.w) << 32);
            *(ull*)&sAh[r * SA + c4 * 4] = h;
            *(ull*)&sAl[r * SA + c4 * 4] = l;
        }
        // B fill: 128 n-rows x 32 k from pre-split W^T
#pragma unroll
        for (int i = 0; i < 4; i++) {
            int f  = t + i * 256;
            int n  = f >> 3;
            int c4 = f & 7;
            *(ull*)&sBh[n * SA + c4 * 4] = *(const ull*)&g_w1h[(size_t)n * FIN + kt + c4 * 4];
            *(ull*)&sBl[n * SA + c4 * 4] = *(const ull*)&g_w1l[(size_t)n * FIN + kt + c4 * 4];
        }
        __syncthreads();

#pragma unroll
        for (int kk = 0; kk < 2; kk++) {
            int k0 = kk * 16 + lk;
            uint32_t ah[2][4], al[2][4];
#pragma unroll
            for (int mi = 0; mi < 2; mi++) {
                int r0 = wm * 32 + mi * 16 + lg;
                ah[mi][0] = *(const uint32_t*)&sAh[r0 * SA + k0];
                ah[mi][1] = *(const uint32_t*)&sAh[(r0 + 8) * SA + k0];
                ah[mi][2] = *(const uint32_t*)&sAh[r0 * SA + k0 + 8];
                ah[mi][3] = *(const uint32_t*)&sAh[(r0 + 8) * SA + k0 + 8];
                al[mi][0] = *(const uint32_t*)&sAl[r0 * SA + k0];
                al[mi][1] = *(const uint32_t*)&sAl[(r0 + 8) * SA + k0];
                al[mi][2] = *(const uint32_t*)&sAl[r0 * SA + k0 + 8];
                al[mi][3] = *(const uint32_t*)&sAl[(r0 + 8) * SA + k0 + 8];
            }
#pragma unroll
            for (int ni = 0; ni < 8; ni++) {
                int c0 = wn * 64 + ni * 8 + lg;
                uint32_t bh0 = *(const uint32_t*)&sBh[c0 * SA + k0];
                uint32_t bh1 = *(const uint32_t*)&sBh[c0 * SA + k0 + 8];
                uint32_t bl0 = *(const uint32_t*)&sBl[c0 * SA + k0];
                uint32_t bl1 = *(const uint32_t*)&sBl[c0 * SA + k0 + 8];
#pragma unroll
                for (int mi = 0; mi < 2; mi++) {
                    MMA_BF16(acc[mi][ni], ah[mi], bh0, bh1);
                    MMA_BF16(acc[mi][ni], ah[mi], bl0, bl1);
                    MMA_BF16(acc[mi][ni], al[mi], bh0, bh1);
                }
            }
        }
        __syncthreads();
    }

    // epilogue: C frag c0,c1 -> [row][col..col+1], c2,c3 -> [row+8][...]
#pragma unroll
    for (int mi = 0; mi < 2; mi++) {
        int r0 = blockRow + wm * 32 + mi * 16 + lg;
#pragma unroll
        for (int ni = 0; ni < 8; ni++) {
            int c = wn * 64 + ni * 8 + (lane & 3) * 2;
            if (r0 < M)
                *(float2*)&g_h1[(size_t)r0 * HID + c] = make_float2(acc[mi][ni][0], acc[mi][ni][1]);
            if (r0 + 8 < M)
                *(float2*)&g_h1[(size_t)(r0 + 8) * HID + c] = make_float2(acc[mi][ni][2], acc[mi][ni][3]);
        }
    }
}

// ------------------ Aggregation 1: warp per node, 128 feats ----------------
__global__ void k_agg1(const float* __restrict__ b1, int n) {
    int w = (blockIdx.x * blockDim.x + threadIdx.x) >> 5;
    if (w >= n) return;
    int l = threadIdx.x & 31;

    float di = g_dis[w];
    float dself = di * di;

    float4 acc = *(const float4*)&g_h1[(size_t)w * HID + l * 4];
    acc.x *= dself; acc.y *= dself; acc.z *= dself; acc.w *= dself;

    int beg = g_off[w], end = g_off[w + 1];
    for (int p = beg; p < end; p++) {
        int   s  = g_esrc[p];
        float wt = g_enrm[p];
        float4 v = *(const float4*)&g_h1[(size_t)s * HID + l * 4];
        acc.x = fmaf(v.x, wt, acc.x);
        acc.y = fmaf(v.y, wt, acc.y);
        acc.z = fmaf(v.z, wt, acc.z);
        acc.w = fmaf(v.w, wt, acc.w);
    }
    float4 bb = *(const float4*)&b1[l * 4];
    acc.x = fmaxf(acc.x + bb.x, 0.f);
    acc.y = fmaxf(acc.y + bb.y, 0.f);
    acc.z = fmaxf(acc.z + bb.z, 0.f);
    acc.w = fmaxf(acc.w + bb.w, 0.f);
    *(float4*)&g_a1[(size_t)w * HID + l * 4] = acc;
}

// --------------------- GEMM2: [N,128] @ [128,40] -> g_h2 -------------------
__global__ __launch_bounds__(256, 2) void k_gemm2(const float* __restrict__ W2, int M) {
    __shared__ float As[16][260];
    __shared__ float Ws[16][NCLS];

    int t  = threadIdx.x;
    int tx = t & 7;
    int ty = t >> 3;
    int blockRow = blockIdx.x * 256;

    float acc[8][5];
#pragma unroll
    for (int i = 0; i < 8; i++)
#pragma unroll
        for (int j = 0; j < 5; j++) acc[i][j] = 0.f;

    for (int kt = 0; kt < HID; kt += 16) {
#pragma unroll
        for (int i = 0; i < 4; i++) {
            int slot = t + i * 256;
            int r  = slot >> 2;
            int c4 = slot & 3;
            int gr = blockRow + r;
            if (gr >= M) gr = M - 1;
            float4 v = *(const float4*)&g_a1[(size_t)gr * HID + kt + c4 * 4];
            As[c4 * 4 + 0][r] = v.x;
            As[c4 * 4 + 1][r] = v.y;
            As[c4 * 4 + 2][r] = v.z;
            As[c4 * 4 + 3][r] = v.w;
        }
        if (t < 160) {
            int r  = t / 10;
            int c4 = t % 10;
            float4 v = *(const float4*)&W2[(size_t)(kt + r) * NCLS + c4 * 4];
            *(float4*)&Ws[r][c4 * 4] = v;
        }
        __syncthreads();

#pragma unroll
        for (int k = 0; k < 16; k++) {
            float a[8], wv[5];
#pragma unroll
            for (int i = 0; i < 8; i++) a[i] = As[k][ty * 8 + i];
#pragma unroll
            for (int j = 0; j < 5; j++) wv[j] = Ws[k][tx * 5 + j];
#pragma unroll
            for (int i = 0; i < 8; i++)
#pragma unroll
                for (int j = 0; j < 5; j++) acc[i][j] = fmaf(a[i], wv[j], acc[i][j]);
        }
        __syncthreads();
    }

#pragma unroll
    for (int i = 0; i < 8; i++) {
        int gr = blockRow + ty * 8 + i;
        if (gr < M) {
#pragma unroll
            for (int j = 0; j < 5; j++)
                g_h2[(size_t)gr * NCLS + tx * 5 + j] = acc[i][j];
        }
    }
}

// ------- Aggregation 2 + bias + log_softmax: warp per node, 40 feats -------
__global__ void k_agg2(const float* __restrict__ b2, float* __restrict__ out, int n) {
    int w = (blockIdx.x * blockDim.x + threadIdx.x) >> 5;
    if (w >= n) return;
    int l = threadIdx.x & 31;
    bool has2 = (l < 8);

    float di = g_dis[w];
    float dself = di * di;

    const float* row = &g_h2[(size_t)w * NCLS];
    float acc0 = row[l] * dself;
    float acc1 = has2 ? row[32 + l] * dself : 0.f;

    int beg = g_off[w], end = g_off[w + 1];
    for (int p = beg; p < end; p++) {
        int   s  = g_esrc[p];
        float wt = g_enrm[p];
        const float* r2 = &g_h2[(size_t)s * NCLS];
        acc0 = fmaf(r2[l], wt, acc0);
        if (has2) acc1 = fmaf(r2[32 + l], wt, acc1);
    }
    acc0 += b2[l];
    if (has2) acc1 += b2[32 + l];

    float m = has2 ? fmaxf(acc0, acc1) : acc0;
#pragma unroll
    for (int o = 16; o >= 1; o >>= 1) m = fmaxf(m, __shfl_xor_sync(0xffffffffu, m, o));
    float e = expf(acc0 - m) + (has2 ? expf(acc1 - m) : 0.f);
#pragma unroll
    for (int o = 16; o >= 1; o >>= 1) e += __shfl_xor_sync(0xffffffffu, e, o);
    float lse = m + logf(e);

    out[(size_t)w * NCLS + l] = acc0 - lse;
    if (has2) out[(size_t)w * NCLS + 32 + l] = acc1 - lse;
}

// --------------------------------- launch ----------------------------------
extern "C" void kernel_launch(void* const* d_in, const int* in_sizes, int n_in,
                              void* d_out, int out_size) {
    const float* x  = (const float*)d_in[0];
    const int*   ei = (const int*)d_in[1];
    const float* W1 = (const float*)d_in[2];
    const float* b1 = (const float*)d_in[3];
    const float* W2 = (const float*)d_in[4];
    const float* b2 = (const float*)d_in[5];
    float*       out = (float*)d_out;

    int N = in_sizes[0] / FIN;       // 100000
    int E = in_sizes[1] / 2;         // 1600000
    int nb = (N + 1023) / 1024;

    // dtype probe + CSR build (parallel scan)
    k_probe<<<1, 1>>>((const unsigned*)d_in[1]);
    k_init<<<(N + 255) / 256, 256>>>(N);
    k_hist<<<(E + 255) / 256, 256>>>(ei, E);
    k_scanA<<<nb, 1024>>>(N);
    k_scanB<<<1, 128>>>(nb);
    k_scanC<<<nb, 1024>>>(N);
    k_scatter<<<(E + 255) / 256, 256>>>(ei, E);

    // Layer 1: HMMA GEMM + aggregate
    k_wconv<<<(FIN * HID + 255) / 256, 256>>>(W1);
    k_gemm1_mma<<<(N + 127) / 128, 256>>>(x, N);
    k_agg1<<<(N * 32 + 255) / 256, 256>>>(b1, N);

    // Layer 2 + log_softmax
    k_gemm2<<<(N + 255) / 256, 256>>>(W2, N);
    k_agg2<<<(N * 32 + 255) / 256, 256>>>(b2, out, N);
}